// round 1
// baseline (speedup 1.0000x reference)
#include <cuda_runtime.h>
#include <cstddef>

// ---------------------------------------------------------------------------
// Shapes (fixed by the problem)
//   B=4, SQ=2048, SK=1024, D=1024
// ---------------------------------------------------------------------------
#define BB   4
#define SQ   2048
#define SK   1024
#define DD   1024

// Scratch (device globals; allocation in kernel_launch is forbidden)
__device__ float g_k  [BB * SK * DD];   // 16 MB
__device__ float g_v  [BB * SK * DD];   // 16 MB
__device__ float g_qy [BB * SQ * DD];   // 32 MB
__device__ float g_inv[BB * SQ * DD];   // 32 MB
__device__ float g_qk [BB * SQ * SK];   // 32 MB

typedef unsigned long long u64;

__device__ __forceinline__ u64 pack_dup(float a) {
    u64 r;
    asm("mov.b64 %0, {%1, %1};" : "=l"(r) : "f"(a));
    return r;
}
__device__ __forceinline__ void fma2(u64 &d, u64 a, u64 b) {
    // packed f32x2 FMA (SASS FFMA2) — 2x fp32 throughput vs scalar FFMA
    asm("fma.rn.f32x2 %0, %1, %2, %0;" : "+l"(d) : "l"(a), "l"(b));
}

// ---------------------------------------------------------------------------
// Tiled GEMM: C[M,N] = A[M,K] * op(B)  (+ epilogue)
//   MODEB = 0 : B is [N,K] row-major (NT, dot of rows)  — linears, qk
//   MODEB = 1 : B is [K,N] row-major (NN)               — attn @ v
//   EPI   = 0 : C += bias[n]            (aux = bias, len N)
//   EPI   = 1 : C /= aux[same index]    (aux shaped like C) — qk/inv_scale
//   EPI   = 2 : none
// Tiles: 128x128x16, 256 threads, 8x8 per thread via f32x2 packed FMA.
// M % 128 == 0, N % 128 == 0, K % 16 == 0 (true for all our shapes).
// ---------------------------------------------------------------------------
template <int MODEB, int EPI>
__global__ __launch_bounds__(256) void gemm128(
    const float* __restrict__ A, const float* __restrict__ B,
    const float* __restrict__ aux, float* __restrict__ C,
    int M, int N, int K,
    size_t sA, size_t sB, size_t sC, size_t sX)
{
    __shared__ float As[16][132];
    __shared__ float Bs[16][132];

    const int tid = threadIdx.x;
    const int tx = tid & 15;        // column group
    const int ty = tid >> 4;        // row group
    const int z  = blockIdx.z;

    A   += (size_t)z * sA;
    B   += (size_t)z * sB;
    C   += (size_t)z * sC;
    aux += (size_t)z * sX;

    const int rm = blockIdx.y * 128;  // row base
    const int cn = blockIdx.x * 128;  // col base

    u64 acc[8][4];
    #pragma unroll
    for (int i = 0; i < 8; i++)
        #pragma unroll
        for (int p = 0; p < 4; p++) acc[i][p] = 0ull;

    for (int k0 = 0; k0 < K; k0 += 16) {
        // ---- load A tile [128 x 16], store transposed As[k][row] ----
        #pragma unroll
        for (int i = 0; i < 2; i++) {
            int f   = tid + i * 256;        // 0..511 float4 slots
            int row = f >> 2;
            int ks  = (f & 3) * 4;
            float4 v = *(const float4*)(A + (size_t)(rm + row) * K + k0 + ks);
            As[ks + 0][row] = v.x;
            As[ks + 1][row] = v.y;
            As[ks + 2][row] = v.z;
            As[ks + 3][row] = v.w;
        }
        // ---- load B tile ----
        if (MODEB == 0) {
            // B[N,K]: same transposed layout as A
            #pragma unroll
            for (int i = 0; i < 2; i++) {
                int f   = tid + i * 256;
                int row = f >> 2;
                int ks  = (f & 3) * 4;
                float4 v = *(const float4*)(B + (size_t)(cn + row) * K + k0 + ks);
                Bs[ks + 0][row] = v.x;
                Bs[ks + 1][row] = v.y;
                Bs[ks + 2][row] = v.z;
                Bs[ks + 3][row] = v.w;
            }
        } else {
            // B[K,N]: direct copy, Bs[k][n]
            #pragma unroll
            for (int i = 0; i < 2; i++) {
                int f  = tid + i * 256;
                int kr = f >> 5;
                int ns = (f & 31) * 4;
                float4 v = *(const float4*)(B + (size_t)(k0 + kr) * N + cn + ns);
                *(float4*)&Bs[kr][ns] = v;
            }
        }
        __syncthreads();

        #pragma unroll
        for (int kk = 0; kk < 16; kk++) {
            float a[8];
            *(float4*)&a[0] = *(const float4*)&As[kk][ty * 8];
            *(float4*)&a[4] = *(const float4*)&As[kk][ty * 8 + 4];
            u64 bv[4];
            const u64* b64 = (const u64*)&Bs[kk][tx * 8];
            bv[0] = b64[0]; bv[1] = b64[1]; bv[2] = b64[2]; bv[3] = b64[3];
            #pragma unroll
            for (int i = 0; i < 8; i++) {
                u64 ad = pack_dup(a[i]);
                #pragma unroll
                for (int p = 0; p < 4; p++) fma2(acc[i][p], ad, bv[p]);
            }
        }
        __syncthreads();
    }

    // ---- epilogue + store ----
    #pragma unroll
    for (int i = 0; i < 8; i++) {
        int r = rm + ty * 8 + i;
        size_t base = (size_t)r * N + cn + tx * 8;
        float c[8];
        #pragma unroll
        for (int p = 0; p < 4; p++) {
            float2 f2 = *(float2*)&acc[i][p];
            c[2 * p + 0] = f2.x;
            c[2 * p + 1] = f2.y;
        }
        if (EPI == 0) {
            #pragma unroll
            for (int j = 0; j < 8; j++) c[j] += aux[cn + tx * 8 + j];
        } else if (EPI == 1) {
            #pragma unroll
            for (int j = 0; j < 8; j++) c[j] /= aux[base + j];
        }
        *(float4*)(C + base)     = *(float4*)&c[0];
        *(float4*)(C + base + 4) = *(float4*)&c[4];
    }
}

// ---------------------------------------------------------------------------
// Row softmax over N=1024, one 256-thread block per row, in place.
// ---------------------------------------------------------------------------
__global__ __launch_bounds__(256) void softmax1024(float* __restrict__ data)
{
    float* p = data + (size_t)blockIdx.x * 1024;
    const int t    = threadIdx.x;
    const int lane = t & 31;
    const int warp = t >> 5;

    __shared__ float redbuf[8];
    __shared__ float stat[2];

    float4 x = *((const float4*)p + t);

    // --- max ---
    float m = fmaxf(fmaxf(x.x, x.y), fmaxf(x.z, x.w));
    #pragma unroll
    for (int o = 16; o > 0; o >>= 1)
        m = fmaxf(m, __shfl_xor_sync(0xffffffffu, m, o));
    if (lane == 0) redbuf[warp] = m;
    __syncthreads();
    if (t == 0) {
        float mm = redbuf[0];
        #pragma unroll
        for (int i = 1; i < 8; i++) mm = fmaxf(mm, redbuf[i]);
        stat[0] = mm;
    }
    __syncthreads();
    const float bm = stat[0];

    // --- exp ---
    x.x = __expf(x.x - bm);
    x.y = __expf(x.y - bm);
    x.z = __expf(x.z - bm);
    x.w = __expf(x.w - bm);

    // --- sum ---
    float s = (x.x + x.y) + (x.z + x.w);
    #pragma unroll
    for (int o = 16; o > 0; o >>= 1)
        s += __shfl_xor_sync(0xffffffffu, s, o);
    __syncthreads();           // protect redbuf reuse
    if (lane == 0) redbuf[warp] = s;
    __syncthreads();
    if (t == 0) {
        float ss = redbuf[0];
        #pragma unroll
        for (int i = 1; i < 8; i++) ss += redbuf[i];
        stat[1] = 1.0f / ss;
    }
    __syncthreads();
    const float r = stat[1];

    x.x *= r; x.y *= r; x.z *= r; x.w *= r;
    *((float4*)p + t) = x;
}

// ---------------------------------------------------------------------------
// kernel_launch
// inputs: 0:x 1:y 2:W1 3:b1 4:W2 5:b2 6:W3 7:b3 8:W4 9:b4 10:W5 11:b5
// ---------------------------------------------------------------------------
extern "C" void kernel_launch(void* const* d_in, const int* in_sizes, int n_in,
                              void* d_out, int out_size)
{
    (void)in_sizes; (void)n_in; (void)out_size;

    const float* x  = (const float*)d_in[0];
    const float* y  = (const float*)d_in[1];
    const float* W2 = (const float*)d_in[4];
    const float* b2 = (const float*)d_in[5];
    const float* W3 = (const float*)d_in[6];
    const float* b3 = (const float*)d_in[7];
    const float* W4 = (const float*)d_in[8];
    const float* b4 = (const float*)d_in[9];
    const float* W5 = (const float*)d_in[10];
    const float* b5 = (const float*)d_in[11];
    float* out = (float*)d_out;

    void *pk, *pv, *pqy, *pinv, *pqk;
    cudaGetSymbolAddress(&pk,   g_k);
    cudaGetSymbolAddress(&pv,   g_v);
    cudaGetSymbolAddress(&pqy,  g_qy);
    cudaGetSymbolAddress(&pinv, g_inv);
    cudaGetSymbolAddress(&pqk,  g_qk);
    float* gk   = (float*)pk;
    float* gv   = (float*)pv;
    float* gqy  = (float*)pqy;
    float* ginv = (float*)pinv;
    float* gqk  = (float*)pqk;

    const dim3 blk(256);

    // linears (batch flattened into M)
    {
        dim3 grid_y(DD / 128, (BB * SK) / 128, 1);   // (8, 32)
        gemm128<0, 0><<<grid_y, blk>>>(y, W2, b2, gk, BB * SK, DD, DD, 0, 0, 0, 0);
        gemm128<0, 0><<<grid_y, blk>>>(y, W3, b3, gv, BB * SK, DD, DD, 0, 0, 0, 0);
        dim3 grid_x(DD / 128, (BB * SQ) / 128, 1);   // (8, 64)
        gemm128<0, 0><<<grid_x, blk>>>(x, W4, b4, gqy,  BB * SQ, DD, DD, 0, 0, 0, 0);
        gemm128<0, 0><<<grid_x, blk>>>(x, W5, b5, ginv, BB * SQ, DD, DD, 0, 0, 0, 0);
    }

    // qk = (qy @ k^T) / inv, per batch
    {
        dim3 grid(SK / 128, SQ / 128, BB);           // (8, 16, 4)
        gemm128<0, 1><<<grid, blk>>>(gqy, gk, ginv, gqk,
                                     SQ, SK, DD,
                                     (size_t)SQ * DD, (size_t)SK * DD,
                                     (size_t)SQ * SK, (size_t)SQ * DD);
    }

    // softmax rows (B*SQ rows of SK=1024)
    softmax1024<<<BB * SQ, blk>>>(gqk);

    // out = attn @ v, per batch
    {
        dim3 grid(DD / 128, SQ / 128, BB);           // (8, 16, 4)
        gemm128<1, 2><<<grid, blk>>>(gqk, gv, nullptr, out,
                                     SQ, DD, SK,
                                     (size_t)SQ * SK, (size_t)SK * DD,
                                     (size_t)SQ * DD, 0);
    }
}

// round 2
// speedup vs baseline: 1.0012x; 1.0012x over previous
#include <cuda_runtime.h>
#include <cstddef>

// ---------------------------------------------------------------------------
// Shapes (fixed by the problem)
//   B=4, SQ=2048, SK=1024, D=1024
// ---------------------------------------------------------------------------
#define BB   4
#define SQ   2048
#define SK   1024
#define DD   1024

// Scratch (device globals; allocation in kernel_launch is forbidden)
__device__ float g_k  [BB * SK * DD];   // 16 MB
__device__ float g_v  [BB * SK * DD];   // 16 MB
__device__ float g_qy [BB * SQ * DD];   // 32 MB
__device__ float g_inv[BB * SQ * DD];   // 32 MB
__device__ float g_qk [BB * SQ * SK];   // 32 MB

typedef unsigned long long u64;

__device__ __forceinline__ u64 pack_dup(float a) {
    u64 r;
    asm("mov.b64 %0, {%1, %1};" : "=l"(r) : "f"(a));
    return r;
}
__device__ __forceinline__ void fma2(u64 &d, u64 a, u64 b) {
    // packed f32x2 FMA (SASS FFMA2) — 2x fp32 throughput vs scalar FFMA
    asm("fma.rn.f32x2 %0, %1, %2, %0;" : "+l"(d) : "l"(a), "l"(b));
}

// ---------------------------------------------------------------------------
// Tiled GEMM: C[M,N] = A[M,K] * op(B)  (+ epilogue)
//   MODEB = 0 : B is [N,K] row-major (NT, dot of rows)  — linears, qk
//   MODEB = 1 : B is [K,N] row-major (NN)               — attn @ v
//   EPI   = 0 : C += bias[n]            (aux = bias, len N)
//   EPI   = 1 : C /= aux[same index]    (aux shaped like C) — qk/inv_scale
//   EPI   = 2 : none
// Tiles: 128x128x16, 256 threads, 8x8 per thread via f32x2 packed FMA.
// M % 128 == 0, N % 128 == 0, K % 16 == 0 (true for all our shapes).
// ---------------------------------------------------------------------------
template <int MODEB, int EPI>
__global__ __launch_bounds__(256) void gemm128(
    const float* __restrict__ A, const float* __restrict__ B,
    const float* __restrict__ aux, float* __restrict__ C,
    int M, int N, int K,
    size_t sA, size_t sB, size_t sC, size_t sX)
{
    __shared__ float As[16][132];
    __shared__ float Bs[16][132];

    const int tid = threadIdx.x;
    const int tx = tid & 15;        // column group
    const int ty = tid >> 4;        // row group
    const int z  = blockIdx.z;

    A   += (size_t)z * sA;
    B   += (size_t)z * sB;
    C   += (size_t)z * sC;
    aux += (size_t)z * sX;

    const int rm = blockIdx.y * 128;  // row base
    const int cn = blockIdx.x * 128;  // col base

    u64 acc[8][4];
    #pragma unroll
    for (int i = 0; i < 8; i++)
        #pragma unroll
        for (int p = 0; p < 4; p++) acc[i][p] = 0ull;

    for (int k0 = 0; k0 < K; k0 += 16) {
        // ---- load A tile [128 x 16], store transposed As[k][row] ----
        #pragma unroll
        for (int i = 0; i < 2; i++) {
            int f   = tid + i * 256;        // 0..511 float4 slots
            int row = f >> 2;
            int ks  = (f & 3) * 4;
            float4 v = *(const float4*)(A + (size_t)(rm + row) * K + k0 + ks);
            As[ks + 0][row] = v.x;
            As[ks + 1][row] = v.y;
            As[ks + 2][row] = v.z;
            As[ks + 3][row] = v.w;
        }
        // ---- load B tile ----
        if (MODEB == 0) {
            // B[N,K]: same transposed layout as A
            #pragma unroll
            for (int i = 0; i < 2; i++) {
                int f   = tid + i * 256;
                int row = f >> 2;
                int ks  = (f & 3) * 4;
                float4 v = *(const float4*)(B + (size_t)(cn + row) * K + k0 + ks);
                Bs[ks + 0][row] = v.x;
                Bs[ks + 1][row] = v.y;
                Bs[ks + 2][row] = v.z;
                Bs[ks + 3][row] = v.w;
            }
        } else {
            // B[K,N]: direct copy, Bs[k][n]
            #pragma unroll
            for (int i = 0; i < 2; i++) {
                int f  = tid + i * 256;
                int kr = f >> 5;
                int ns = (f & 31) * 4;
                float4 v = *(const float4*)(B + (size_t)(k0 + kr) * N + cn + ns);
                *(float4*)&Bs[kr][ns] = v;
            }
        }
        __syncthreads();

        #pragma unroll
        for (int kk = 0; kk < 16; kk++) {
            float a[8];
            *(float4*)&a[0] = *(const float4*)&As[kk][ty * 8];
            *(float4*)&a[4] = *(const float4*)&As[kk][ty * 8 + 4];
            u64 bv[4];
            const u64* b64 = (const u64*)&Bs[kk][tx * 8];
            bv[0] = b64[0]; bv[1] = b64[1]; bv[2] = b64[2]; bv[3] = b64[3];
            #pragma unroll
            for (int i = 0; i < 8; i++) {
                u64 ad = pack_dup(a[i]);
                #pragma unroll
                for (int p = 0; p < 4; p++) fma2(acc[i][p], ad, bv[p]);
            }
        }
        __syncthreads();
    }

    // ---- epilogue + store ----
    #pragma unroll
    for (int i = 0; i < 8; i++) {
        int r = rm + ty * 8 + i;
        size_t base = (size_t)r * N + cn + tx * 8;
        float c[8];
        #pragma unroll
        for (int p = 0; p < 4; p++) {
            float2 f2 = *(float2*)&acc[i][p];
            c[2 * p + 0] = f2.x;
            c[2 * p + 1] = f2.y;
        }
        if (EPI == 0) {
            #pragma unroll
            for (int j = 0; j < 8; j++) c[j] += aux[cn + tx * 8 + j];
        } else if (EPI == 1) {
            #pragma unroll
            for (int j = 0; j < 8; j++) c[j] /= aux[base + j];
        }
        *(float4*)(C + base)     = *(float4*)&c[0];
        *(float4*)(C + base + 4) = *(float4*)&c[4];
    }
}

// ---------------------------------------------------------------------------
// Row softmax over N=1024, one 256-thread block per row, in place.
// ---------------------------------------------------------------------------
__global__ __launch_bounds__(256) void softmax1024(float* __restrict__ data)
{
    float* p = data + (size_t)blockIdx.x * 1024;
    const int t    = threadIdx.x;
    const int lane = t & 31;
    const int warp = t >> 5;

    __shared__ float redbuf[8];
    __shared__ float stat[2];

    float4 x = *((const float4*)p + t);

    // --- max ---
    float m = fmaxf(fmaxf(x.x, x.y), fmaxf(x.z, x.w));
    #pragma unroll
    for (int o = 16; o > 0; o >>= 1)
        m = fmaxf(m, __shfl_xor_sync(0xffffffffu, m, o));
    if (lane == 0) redbuf[warp] = m;
    __syncthreads();
    if (t == 0) {
        float mm = redbuf[0];
        #pragma unroll
        for (int i = 1; i < 8; i++) mm = fmaxf(mm, redbuf[i]);
        stat[0] = mm;
    }
    __syncthreads();
    const float bm = stat[0];

    // --- exp ---
    x.x = __expf(x.x - bm);
    x.y = __expf(x.y - bm);
    x.z = __expf(x.z - bm);
    x.w = __expf(x.w - bm);

    // --- sum ---
    float s = (x.x + x.y) + (x.z + x.w);
    #pragma unroll
    for (int o = 16; o > 0; o >>= 1)
        s += __shfl_xor_sync(0xffffffffu, s, o);
    __syncthreads();           // protect redbuf reuse
    if (lane == 0) redbuf[warp] = s;
    __syncthreads();
    if (t == 0) {
        float ss = redbuf[0];
        #pragma unroll
        for (int i = 1; i < 8; i++) ss += redbuf[i];
        stat[1] = 1.0f / ss;
    }
    __syncthreads();
    const float r = stat[1];

    x.x *= r; x.y *= r; x.z *= r; x.w *= r;
    *((float4*)p + t) = x;
}

// ---------------------------------------------------------------------------
// kernel_launch
// inputs: 0:x 1:y 2:W1 3:b1 4:W2 5:b2 6:W3 7:b3 8:W4 9:b4 10:W5 11:b5
// ---------------------------------------------------------------------------
extern "C" void kernel_launch(void* const* d_in, const int* in_sizes, int n_in,
                              void* d_out, int out_size)
{
    (void)in_sizes; (void)n_in; (void)out_size;

    const float* x  = (const float*)d_in[0];
    const float* y  = (const float*)d_in[1];
    const float* W2 = (const float*)d_in[4];
    const float* b2 = (const float*)d_in[5];
    const float* W3 = (const float*)d_in[6];
    const float* b3 = (const float*)d_in[7];
    const float* W4 = (const float*)d_in[8];
    const float* b4 = (const float*)d_in[9];
    const float* W5 = (const float*)d_in[10];
    const float* b5 = (const float*)d_in[11];
    float* out = (float*)d_out;

    void *pk, *pv, *pqy, *pinv, *pqk;
    cudaGetSymbolAddress(&pk,   g_k);
    cudaGetSymbolAddress(&pv,   g_v);
    cudaGetSymbolAddress(&pqy,  g_qy);
    cudaGetSymbolAddress(&pinv, g_inv);
    cudaGetSymbolAddress(&pqk,  g_qk);
    float* gk   = (float*)pk;
    float* gv   = (float*)pv;
    float* gqy  = (float*)pqy;
    float* ginv = (float*)pinv;
    float* gqk  = (float*)pqk;

    const dim3 blk(256);

    // linears (batch flattened into M)
    {
        dim3 grid_y(DD / 128, (BB * SK) / 128, 1);   // (8, 32)
        gemm128<0, 0><<<grid_y, blk>>>(y, W2, b2, gk, BB * SK, DD, DD, 0, 0, 0, 0);
        gemm128<0, 0><<<grid_y, blk>>>(y, W3, b3, gv, BB * SK, DD, DD, 0, 0, 0, 0);
        dim3 grid_x(DD / 128, (BB * SQ) / 128, 1);   // (8, 64)
        gemm128<0, 0><<<grid_x, blk>>>(x, W4, b4, gqy,  BB * SQ, DD, DD, 0, 0, 0, 0);
        gemm128<0, 0><<<grid_x, blk>>>(x, W5, b5, ginv, BB * SQ, DD, DD, 0, 0, 0, 0);
    }

    // qk = (qy @ k^T) / inv, per batch
    {
        dim3 grid(SK / 128, SQ / 128, BB);           // (8, 16, 4)
        gemm128<0, 1><<<grid, blk>>>(gqy, gk, ginv, gqk,
                                     SQ, SK, DD,
                                     (size_t)SQ * DD, (size_t)SK * DD,
                                     (size_t)SQ * SK, (size_t)SQ * DD);
    }

    // softmax rows (B*SQ rows of SK=1024)
    softmax1024<<<BB * SQ, blk>>>(gqk);

    // out = attn @ v, per batch
    {
        dim3 grid(DD / 128, SQ / 128, BB);           // (8, 16, 4)
        gemm128<1, 2><<<grid, blk>>>(gqk, gv, nullptr, out,
                                     SQ, DD, SK,
                                     (size_t)SQ * SK, (size_t)SK * DD,
                                     (size_t)SQ * DD, 0);
    }
}